// round 10
// baseline (speedup 1.0000x reference)
#include <cuda_runtime.h>
#include <cstdint>

// ---------------- problem constants ----------------
#define S  2048
#define E  1024
#define H  1024
#define V  32000
#define NLOGB 4000        // k_logits blocks
#define PREF_BYTES ((size_t)24000 * H * 4)   // ~96 MB of W_out prefetched to L2

// ---------------- device scratch (no allocs allowed) ----------------
__device__ __align__(16) float g_gates[4 * H];
__device__ __align__(16) float g_h[H];
__device__ __align__(16) float g_u[H];
__device__ __align__(16) float g_scores[S];
__device__ __align__(16) float g_w[S];
__device__ __align__(16) float g_context[E];
__device__ __align__(16) float g_xt[H];
__device__ __align__(16) float g_C[(size_t)S * H];   // attention GEMM output (8 MB)
__device__ __align__(16) float g_lp[NLOGB];          // per-block exp-sum partials

__device__ __forceinline__ float sigf(float x) { return 1.0f / (1.0f + expf(-x)); }

__device__ __forceinline__ float warp_sum(float s) {
#pragma unroll
    for (int o = 16; o; o >>= 1) s += __shfl_xor_sync(0xFFFFFFFFu, s, o);
    return s;
}

__device__ __forceinline__ void mma_tf32(float* c, const uint32_t* a, uint32_t b0, uint32_t b1) {
    asm volatile(
        "mma.sync.aligned.m16n8k8.row.col.f32.tf32.tf32.f32 "
        "{%0,%1,%2,%3}, {%4,%5,%6,%7}, {%8,%9}, {%0,%1,%2,%3};\n"
        : "+f"(c[0]), "+f"(c[1]), "+f"(c[2]), "+f"(c[3])
        : "r"(a[0]), "r"(a[1]), "r"(a[2]), "r"(a[3]), "r"(b0), "r"(b1));
}

__device__ __forceinline__ void cp16(uint32_t dst_smem, const void* src) {
    asm volatile("cp.async.cg.shared.global [%0], [%1], 16;\n" :: "r"(dst_smem), "l"(src));
}
__device__ __forceinline__ void cp_commit() {
    asm volatile("cp.async.commit_group;\n");
}
template <int N>
__device__ __forceinline__ void cp_wait() {
    asm volatile("cp.async.wait_group %0;\n" :: "n"(N));
}

// ---------------- K_MAIN: fat kernel = attention GEMM + LSTM gates + W_out prefetch ----
// blocks [0,256)   : GEMM tile (s-tile = bid & 31, h-tile = bid >> 5)
// blocks [256,768) : gates rows
// blocks [768,1024): W_out L2 prefetch
#define BM 64
#define BN 128
#define BKC 32
#define PADK 36
#define NSTAGE 4
#define NKC (E / BKC)
#define STAGE_FLOATS ((BM + BN) * PADK)
#define ATT_SMEM_BYTES (NSTAGE * STAGE_FLOATS * 4)

__global__ void __launch_bounds__(256, 2)
k_main(const float* __restrict__ enc, const float* __restrict__ W_att,
       const float* __restrict__ W_ih, const float* __restrict__ b_ih,
       const float* __restrict__ W_hh, const float* __restrict__ b_hh,
       const float* __restrict__ last_ctx, const float* __restrict__ emb,
       const int* __restrict__ word, const float* __restrict__ h0,
       const float* __restrict__ W_out) {
    extern __shared__ float smem_dyn[];

    int bid  = blockIdx.x;
    int tid  = threadIdx.x;
    int wid  = tid >> 5;
    int lane = tid & 31;

    if (bid >= 768) {
        // ---- W_out prefetch into L2 ----
        const char* base = (const char*)W_out;
        size_t line = ((size_t)(bid - 768) * 256 + tid);
#pragma unroll
        for (int it = 0; it < 12; it++) {
            size_t off = (line + (size_t)it * 65536) * 128;
            if (off < PREF_BYTES)
                asm volatile("prefetch.global.L2 [%0];" :: "l"(base + off));
        }
        return;
    }

    if (bid >= 256) {
        // ---- LSTM gates matvec: row r ----
        int r = (bid - 256) * 8 + wid;
        const float4* xe4 = (const float4*)(emb + (size_t)word[0] * E);
        const float4* lc4 = (const float4*)last_ctx;
        const float4* h04 = (const float4*)h0;
        const float4* wi4 = (const float4*)(W_ih + (size_t)r * (E + H));
        const float4* wh4 = (const float4*)(W_hh + (size_t)r * H);
        float s = 0.f;
#pragma unroll
        for (int q = 0; q < 8; q++) {
            int k = lane + 32 * q;
            float4 a = wi4[k];       float4 b = lc4[k];
            s += a.x * b.x + a.y * b.y + a.z * b.z + a.w * b.w;
            float4 a2 = wi4[256 + k]; float4 b2 = xe4[k];
            s += a2.x * b2.x + a2.y * b2.y + a2.z * b2.z + a2.w * b2.w;
            float4 a3 = wh4[k];      float4 b3 = h04[k];
            s += a3.x * b3.x + a3.y * b3.y + a3.z * b3.z + a3.w * b3.w;
        }
        s = warp_sum(s);
        if (lane == 0) g_gates[r] = s + b_ih[r] + b_hh[r];
        return;
    }

    // ---- attention GEMM tile ----
    int warp_m = wid >> 2;
    int warp_n = wid & 3;
    int gid  = lane >> 2;
    int tid4 = lane & 3;
    int s0 = (bid & 31) * BM;
    int h0g = (bid >> 5) * BN;

    uint32_t smem_u32;
    {
        uint64_t tmp;
        asm("cvta.to.shared.u64 %0, %1;" : "=l"(tmp) : "l"(smem_dyn));
        smem_u32 = (uint32_t)tmp;
    }

    float acc[2][4][4];
#pragma unroll
    for (int mt = 0; mt < 2; mt++)
#pragma unroll
        for (int nt = 0; nt < 4; nt++)
#pragma unroll
            for (int r = 0; r < 4; r++) acc[mt][nt][r] = 0.f;

    int rA[2], cA[2], rB[4], cB[4];
#pragma unroll
    for (int i = 0; i < 2; i++) { int f = tid + 256 * i; rA[i] = f >> 3; cA[i] = f & 7; }
#pragma unroll
    for (int i = 0; i < 4; i++) { int f = tid + 256 * i; rB[i] = f >> 3; cB[i] = f & 7; }

    const float* encp = enc   + (size_t)s0 * E;
    const float* wap  = W_att + (size_t)h0g * (H + E) + H;

#define ISSUE(kc_) do {                                                             \
        int st_ = (kc_) & (NSTAGE - 1);                                             \
        uint32_t abase_ = smem_u32 + st_ * (STAGE_FLOATS * 4);                      \
        uint32_t bbase_ = abase_ + BM * PADK * 4;                                   \
        int kofs_ = (kc_) * BKC;                                                    \
        _Pragma("unroll")                                                           \
        for (int i = 0; i < 2; i++)                                                 \
            cp16(abase_ + (rA[i] * PADK + cA[i] * 4) * 4,                           \
                 encp + (size_t)rA[i] * E + kofs_ + cA[i] * 4);                     \
        _Pragma("unroll")                                                           \
        for (int i = 0; i < 4; i++)                                                 \
            cp16(bbase_ + (rB[i] * PADK + cB[i] * 4) * 4,                           \
                 wap + (size_t)rB[i] * (H + E) + kofs_ + cB[i] * 4);                \
        cp_commit();                                                                \
    } while (0)

    ISSUE(0); ISSUE(1); ISSUE(2);

    for (int kc = 0; kc < NKC; kc++) {
        cp_wait<2>();
        __syncthreads();
        if (kc + 3 < NKC) ISSUE(kc + 3);

        int st = kc & (NSTAGE - 1);
        const uint32_t* As_s = (const uint32_t*)(smem_dyn + st * STAGE_FLOATS);
        const uint32_t* Bs_s = As_s + BM * PADK;

#pragma unroll
        for (int ks = 0; ks < BKC / 8; ks++) {
            int kb = ks * 8;
            uint32_t af[2][4];
#pragma unroll
            for (int mt = 0; mt < 2; mt++) {
                int row = warp_m * 32 + mt * 16 + gid;
                af[mt][0] = As_s[row * PADK + kb + tid4];
                af[mt][1] = As_s[(row + 8) * PADK + kb + tid4];
                af[mt][2] = As_s[row * PADK + kb + tid4 + 4];
                af[mt][3] = As_s[(row + 8) * PADK + kb + tid4 + 4];
            }
#pragma unroll
            for (int nt = 0; nt < 4; nt++) {
                int col = warp_n * 32 + nt * 8 + gid;
                uint32_t b0 = Bs_s[col * PADK + kb + tid4];
                uint32_t b1 = Bs_s[col * PADK + kb + tid4 + 4];
#pragma unroll
                for (int mt = 0; mt < 2; mt++)
                    mma_tf32(acc[mt][nt], af[mt], b0, b1);
            }
        }
    }
#undef ISSUE

#pragma unroll
    for (int mt = 0; mt < 2; mt++) {
        int srow = s0 + warp_m * 32 + mt * 16 + gid;
#pragma unroll
        for (int nt = 0; nt < 4; nt++) {
            int hcol = h0g + warp_n * 32 + nt * 8 + 2 * tid4;
            float2 v0 = make_float2(acc[mt][nt][0], acc[mt][nt][1]);
            float2 v1 = make_float2(acc[mt][nt][2], acc[mt][nt][3]);
            *(float2*)&g_C[(size_t)srow * H + hcol]       = v0;
            *(float2*)&g_C[(size_t)(srow + 8) * H + hcol] = v1;
        }
    }
}

// ---------------- K2: fused LSTM cell + u = W_att[:,:H]@h + b_att ----------------
__global__ void k_cell_u(const float* __restrict__ c0, const float* __restrict__ W_att,
                         const float* __restrict__ b_att, float* __restrict__ out) {
    __shared__ float sh[H];
    int tid  = threadIdx.x;
    int wid  = tid >> 5;
    int lane = tid & 31;

#pragma unroll
    for (int j = 0; j < 4; j++) {
        int t = tid + 256 * j;
        float ig = sigf(g_gates[t]);
        float fg = sigf(g_gates[H + t]);
        float gg = tanhf(g_gates[2 * H + t]);
        float og = sigf(g_gates[3 * H + t]);
        float c  = fg * c0[t] + ig * gg;
        float h  = og * tanhf(c);
        sh[t] = h;
        if (blockIdx.x == 0) {
            g_h[t] = h;
            out[V + t]     = h;
            out[V + H + t] = c;
            g_context[t]   = 0.f;
        }
    }
    __syncthreads();

    int r = blockIdx.x * 8 + wid;
    const float4* wa4 = (const float4*)(W_att + (size_t)r * (H + E));
    const float4* h4  = (const float4*)sh;
    float s = 0.f;
#pragma unroll
    for (int q = 0; q < 8; q++) {
        int k = lane + 32 * q;
        float4 a = wa4[k]; float4 b = h4[k];
        s += a.x * b.x + a.y * b.y + a.z * b.z + a.w * b.w;
    }
    s = warp_sum(s);
    if (lane == 0) g_u[r] = s + b_att[r];
}

// ---------------- K4: score epilogue: warp-per-row, 8 float4/lane ----------------
__global__ void k_score(const float* __restrict__ v) {
    int wid  = threadIdx.x >> 5;
    int lane = threadIdx.x & 31;
    int row  = blockIdx.x * 8 + wid;

    const float4* c4 = (const float4*)(g_C + (size_t)row * H);
    const float4* u4 = (const float4*)g_u;
    const float4* v4 = (const float4*)v;

    float p = 0.f;
#pragma unroll
    for (int q = 0; q < 8; q++) {
        int k = lane + 32 * q;
        float4 c = c4[k]; float4 u = u4[k]; float4 vv = v4[k];
        p += vv.x * tanhf(c.x + u.x) + vv.y * tanhf(c.y + u.y)
           + vv.z * tanhf(c.z + u.z) + vv.w * tanhf(c.w + u.w);
    }
    p = warp_sum(p);
    if (lane == 0) g_scores[row] = p;
}

// ---------------- K4b: softmax over scores[2048] -> g_w ----------------
__global__ void k_softmax(float* __restrict__ out) {
    __shared__ float red[1024];
    int t = threadIdx.x;
    float a = g_scores[t], b = g_scores[t + 1024];
    float m = fmaxf(a, b);
    red[t] = m; __syncthreads();
    for (int o = 512; o; o >>= 1) { if (t < o) red[t] = fmaxf(red[t], red[t + o]); __syncthreads(); }
    m = red[0]; __syncthreads();
    float e0 = expf(a - m), e1 = expf(b - m);
    red[t] = e0 + e1; __syncthreads();
    for (int o = 512; o; o >>= 1) { if (t < o) red[t] += red[t + o]; __syncthreads(); }
    float inv = 1.0f / red[0];
    float w0 = e0 * inv, w1 = e1 * inv;
    g_w[t] = w0;             g_w[t + 1024] = w1;
    out[V + 3 * H + t] = w0; out[V + 3 * H + t + 1024] = w1;
}

// ---------------- K5: context = w @ enc ----------------
__global__ void k_ctx(const float* __restrict__ enc) {
    __shared__ float sw[64];
    int tid = threadIdx.x;
    int e   = blockIdx.x * 256 + tid;
    int s0c = blockIdx.y * 64;
    if (tid < 64) sw[tid] = g_w[s0c + tid];
    __syncthreads();
    float acc = 0.f;
#pragma unroll 8
    for (int s = 0; s < 64; s++)
        acc += sw[s] * enc[(size_t)(s0c + s) * E + e];
    atomicAdd(&g_context[e], acc);
}

// ---------------- K6: x_t = tanh(W_ah @ [context, h] + b_ah) ----------------
__global__ void k_xt(const float* __restrict__ W_ah, const float* __restrict__ b_ah,
                     float* __restrict__ out) {
    int r    = blockIdx.x * 8 + (threadIdx.x >> 5);
    int lane = threadIdx.x & 31;
    const float4* wa4 = (const float4*)(W_ah + (size_t)r * (E + H));
    const float4* c4  = (const float4*)g_context;
    const float4* h4  = (const float4*)g_h;
    float s = 0.f;
#pragma unroll
    for (int q = 0; q < 8; q++) {
        int k = lane + 32 * q;
        float4 a = wa4[k];        float4 b = c4[k];
        s += a.x * b.x + a.y * b.y + a.z * b.z + a.w * b.w;
        float4 a2 = wa4[256 + k]; float4 b2 = h4[k];
        s += a2.x * b2.x + a2.y * b2.y + a2.z * b2.z + a2.w * b2.w;
    }
    s = warp_sum(s);
    if (lane == 0) {
        float xt = tanhf(s + b_ah[r]);
        g_xt[r] = xt;
        out[V + 2 * H + r] = xt;
    }
}

// ---------------- K7: logits = W_out @ x_t + b_out, + per-block exp-sum partials ----
__global__ void k_logits(const float* __restrict__ W_out, const float* __restrict__ b_out,
                         float* __restrict__ out) {
    __shared__ float sred[8];
    int tid  = threadIdx.x;
    int wid  = tid >> 5;
    int lane = tid & 31;
    int r    = blockIdx.x * 8 + wid;
    const float4* w4 = (const float4*)(W_out + (size_t)r * H);
    const float4* x4 = (const float4*)g_xt;
    float s = 0.f;
#pragma unroll
    for (int q = 0; q < 8; q++) {
        int k = lane + 32 * q;
        float4 a = w4[k]; float4 b = x4[k];
        s += a.x * b.x + a.y * b.y + a.z * b.z + a.w * b.w;
    }
    s = warp_sum(s);
    if (lane == 0) {
        float val = s + b_out[r];
        out[r] = val;
        sred[wid] = expf(val);
    }
    __syncthreads();
    if (tid == 0) {
        float p = 0.f;
#pragma unroll
        for (int i = 0; i < 8; i++) p += sred[i];
        g_lp[blockIdx.x] = p;
    }
}

// ---------------- K8: log-softmax ----------------
__global__ void k_logsoftmax(float* __restrict__ out) {
    __shared__ float red[256];
    int tid = threadIdx.x;
    float p = 0.f;
    for (int i = tid; i < NLOGB; i += 256) p += g_lp[i];
    red[tid] = p; __syncthreads();
    for (int o = 128; o; o >>= 1) { if (tid < o) red[tid] += red[tid + o]; __syncthreads(); }
    float l = logf(red[0]);
    int i = blockIdx.x * 256 + tid;
    out[i] = out[i] - l;
}

// ---------------- launch (single stream, no allocations) ----------------
extern "C" void kernel_launch(void* const* d_in, const int* in_sizes, int n_in,
                              void* d_out, int out_size) {
    const float* enc      = (const float*)d_in[0];
    const int*   word     = (const int*)  d_in[1];
    const float* last_ctx = (const float*)d_in[2];
    const float* h0       = (const float*)d_in[3];
    const float* c0       = (const float*)d_in[4];
    const float* emb      = (const float*)d_in[5];
    const float* W_ih     = (const float*)d_in[6];
    const float* b_ih     = (const float*)d_in[7];
    const float* W_hh     = (const float*)d_in[8];
    const float* b_hh     = (const float*)d_in[9];
    const float* W_att    = (const float*)d_in[10];
    const float* b_att    = (const float*)d_in[11];
    const float* v        = (const float*)d_in[12];
    const float* W_ah     = (const float*)d_in[13];
    const float* b_ah     = (const float*)d_in[14];
    const float* W_out    = (const float*)d_in[15];
    const float* b_out    = (const float*)d_in[16];
    float* out = (float*)d_out;

    cudaFuncSetAttribute(k_main, cudaFuncAttributeMaxDynamicSharedMemorySize, ATT_SMEM_BYTES);

    k_main<<<1024, 256, ATT_SMEM_BYTES>>>(enc, W_att, W_ih, b_ih, W_hh, b_hh,
                                          last_ctx, emb, word, h0, W_out);
    k_cell_u<<<128, 256>>>(c0, W_att, b_att, out);
    k_score<<<S / 8, 256>>>(v);
    k_softmax<<<1, 1024>>>(out);
    dim3 g5(E / 256, S / 64);
    k_ctx<<<g5, 256>>>(enc);
    k_xt<<<128, 256>>>(W_ah, b_ah, out);
    k_logits<<<NLOGB, 256>>>(W_out, b_out, out);
    k_logsoftmax<<<V / 256, 256>>>(out);
}

// round 11
// speedup vs baseline: 1.0777x; 1.0777x over previous
#include <cuda_runtime.h>
#include <cstdint>

// ---------------- problem constants ----------------
#define S  2048
#define E  1024
#define H  1024
#define V  32000
#define NLOGB 4000        // k_logits blocks
#define PREF_BYTES ((size_t)24000 * H * 4)   // ~96 MB of W_out prefetched to L2

// ---------------- device scratch (no allocs allowed) ----------------
__device__ __align__(16) float g_gates[4 * H];
__device__ __align__(16) float g_h[H];
__device__ __align__(16) float g_u[H];
__device__ __align__(16) float g_scores[S];
__device__ __align__(16) float g_context[E];
__device__ __align__(16) float g_xt[H];
__device__ __align__(16) float g_C[(size_t)S * H];   // attention GEMM output (8 MB)
__device__ __align__(16) float g_lp[NLOGB];          // per-block exp-sum partials
__device__ float g_sumexp;                           // softmax denominator

__device__ __forceinline__ float sigf(float x) { return 1.0f / (1.0f + expf(-x)); }

__device__ __forceinline__ float warp_sum(float s) {
#pragma unroll
    for (int o = 16; o; o >>= 1) s += __shfl_xor_sync(0xFFFFFFFFu, s, o);
    return s;
}

__device__ __forceinline__ void mma_tf32(float* c, const uint32_t* a, uint32_t b0, uint32_t b1) {
    asm volatile(
        "mma.sync.aligned.m16n8k8.row.col.f32.tf32.tf32.f32 "
        "{%0,%1,%2,%3}, {%4,%5,%6,%7}, {%8,%9}, {%0,%1,%2,%3};\n"
        : "+f"(c[0]), "+f"(c[1]), "+f"(c[2]), "+f"(c[3])
        : "r"(a[0]), "r"(a[1]), "r"(a[2]), "r"(a[3]), "r"(b0), "r"(b1));
}

__device__ __forceinline__ void cp16(uint32_t dst_smem, const void* src) {
    asm volatile("cp.async.cg.shared.global [%0], [%1], 16;\n" :: "r"(dst_smem), "l"(src));
}
__device__ __forceinline__ void cp_commit() {
    asm volatile("cp.async.commit_group;\n");
}
template <int N>
__device__ __forceinline__ void cp_wait() {
    asm volatile("cp.async.wait_group %0;\n" :: "n"(N));
}

// ---------------- K0: W_out prefetch into L2 (side stream, first) ----------------
__global__ void k_prefetch(const float* __restrict__ W_out) {
    const char* base = (const char*)W_out;
    size_t line = (size_t)blockIdx.x * 256 + threadIdx.x;
#pragma unroll
    for (int it = 0; it < 4; it++) {
        size_t off = (line + (size_t)it * 196608) * 128;
        if (off < PREF_BYTES)
            asm volatile("prefetch.global.L2 [%0];" :: "l"(base + off));
    }
}

// ---------------- K1: LSTM gates matvec (side stream) ----------------
__global__ void k_gates(const float* __restrict__ W_ih, const float* __restrict__ b_ih,
                        const float* __restrict__ W_hh, const float* __restrict__ b_hh,
                        const float* __restrict__ last_ctx, const float* __restrict__ emb,
                        const int* __restrict__ word, const float* __restrict__ h0) {
    int r    = blockIdx.x * 8 + (threadIdx.x >> 5);
    int lane = threadIdx.x & 31;
    const float4* xe4 = (const float4*)(emb + (size_t)word[0] * E);
    const float4* lc4 = (const float4*)last_ctx;
    const float4* h04 = (const float4*)h0;
    const float4* wi4 = (const float4*)(W_ih + (size_t)r * (E + H));
    const float4* wh4 = (const float4*)(W_hh + (size_t)r * H);

    float s = 0.f;
#pragma unroll
    for (int q = 0; q < 8; q++) {
        int k = lane + 32 * q;
        float4 a = wi4[k];       float4 b = lc4[k];
        s += a.x * b.x + a.y * b.y + a.z * b.z + a.w * b.w;
        float4 a2 = wi4[256 + k]; float4 b2 = xe4[k];
        s += a2.x * b2.x + a2.y * b2.y + a2.z * b2.z + a2.w * b2.w;
        float4 a3 = wh4[k];      float4 b3 = h04[k];
        s += a3.x * b3.x + a3.y * b3.y + a3.z * b3.z + a3.w * b3.w;
    }
    s = warp_sum(s);
    if (lane == 0) g_gates[r] = s + b_ih[r] + b_hh[r];
}

// ---------------- K2: fused LSTM cell + u = W_att[:,:H]@h + b_att (side stream) ----
__global__ void k_cell_u(const float* __restrict__ c0, const float* __restrict__ W_att,
                         const float* __restrict__ b_att, float* __restrict__ out) {
    __shared__ float sh[H];
    int tid  = threadIdx.x;
    int wid  = tid >> 5;
    int lane = tid & 31;

#pragma unroll
    for (int j = 0; j < 4; j++) {
        int t = tid + 256 * j;
        float ig = sigf(g_gates[t]);
        float fg = sigf(g_gates[H + t]);
        float gg = tanhf(g_gates[2 * H + t]);
        float og = sigf(g_gates[3 * H + t]);
        float c  = fg * c0[t] + ig * gg;
        float h  = og * tanhf(c);
        sh[t] = h;
        if (blockIdx.x == 0) {
            g_h[t] = h;
            out[V + t]     = h;
            out[V + H + t] = c;
            g_context[t]   = 0.f;
        }
    }
    if (blockIdx.x == 0 && tid == 0) g_sumexp = 0.f;
    __syncthreads();

    int r = blockIdx.x * 8 + wid;
    const float4* wa4 = (const float4*)(W_att + (size_t)r * (H + E));
    const float4* h4  = (const float4*)sh;
    float s = 0.f;
#pragma unroll
    for (int q = 0; q < 8; q++) {
        int k = lane + 32 * q;
        float4 a = wa4[k]; float4 b = h4[k];
        s += a.x * b.x + a.y * b.y + a.z * b.z + a.w * b.w;
    }
    s = warp_sum(s);
    if (lane == 0) g_u[r] = s + b_att[r];
}

// ---------------- K3: attention GEMM (tf32 mma.sync, cp.async 4-stage) ----------------
#define BM 64
#define BN 128
#define BKC 32
#define PADK 36
#define NSTAGE 4
#define NKC (E / BKC)
#define STAGE_FLOATS ((BM + BN) * PADK)
#define ATT_SMEM_BYTES (NSTAGE * STAGE_FLOATS * 4)

__global__ void __launch_bounds__(256, 2)
k_att_gemm(const float* __restrict__ enc, const float* __restrict__ W_att) {
    extern __shared__ float smem_dyn[];

    int tid  = threadIdx.x;
    int wid  = tid >> 5;
    int lane = tid & 31;
    int warp_m = wid >> 2;
    int warp_n = wid & 3;
    int gid  = lane >> 2;
    int tid4 = lane & 3;
    int s0 = blockIdx.x * BM;
    int h0 = blockIdx.y * BN;

    uint32_t smem_u32;
    {
        uint64_t tmp;
        asm("cvta.to.shared.u64 %0, %1;" : "=l"(tmp) : "l"(smem_dyn));
        smem_u32 = (uint32_t)tmp;
    }

    float acc[2][4][4];
#pragma unroll
    for (int mt = 0; mt < 2; mt++)
#pragma unroll
        for (int nt = 0; nt < 4; nt++)
#pragma unroll
            for (int r = 0; r < 4; r++) acc[mt][nt][r] = 0.f;

    int rA[2], cA[2], rB[4], cB[4];
#pragma unroll
    for (int i = 0; i < 2; i++) { int f = tid + 256 * i; rA[i] = f >> 3; cA[i] = f & 7; }
#pragma unroll
    for (int i = 0; i < 4; i++) { int f = tid + 256 * i; rB[i] = f >> 3; cB[i] = f & 7; }

    const float* encp = enc   + (size_t)s0 * E;
    const float* wap  = W_att + (size_t)h0 * (H + E) + H;

#define ISSUE(kc_) do {                                                             \
        int st_ = (kc_) & (NSTAGE - 1);                                             \
        uint32_t abase_ = smem_u32 + st_ * (STAGE_FLOATS * 4);                      \
        uint32_t bbase_ = abase_ + BM * PADK * 4;                                   \
        int kofs_ = (kc_) * BKC;                                                    \
        _Pragma("unroll")                                                           \
        for (int i = 0; i < 2; i++)                                                 \
            cp16(abase_ + (rA[i] * PADK + cA[i] * 4) * 4,                           \
                 encp + (size_t)rA[i] * E + kofs_ + cA[i] * 4);                     \
        _Pragma("unroll")                                                           \
        for (int i = 0; i < 4; i++)                                                 \
            cp16(bbase_ + (rB[i] * PADK + cB[i] * 4) * 4,                           \
                 wap + (size_t)rB[i] * (H + E) + kofs_ + cB[i] * 4);                \
        cp_commit();                                                                \
    } while (0)

    ISSUE(0); ISSUE(1); ISSUE(2);

    for (int kc = 0; kc < NKC; kc++) {
        cp_wait<2>();
        __syncthreads();
        if (kc + 3 < NKC) ISSUE(kc + 3);

        int st = kc & (NSTAGE - 1);
        const uint32_t* As_s = (const uint32_t*)(smem_dyn + st * STAGE_FLOATS);
        const uint32_t* Bs_s = As_s + BM * PADK;

#pragma unroll
        for (int ks = 0; ks < BKC / 8; ks++) {
            int kb = ks * 8;
            uint32_t af[2][4];
#pragma unroll
            for (int mt = 0; mt < 2; mt++) {
                int row = warp_m * 32 + mt * 16 + gid;
                af[mt][0] = As_s[row * PADK + kb + tid4];
                af[mt][1] = As_s[(row + 8) * PADK + kb + tid4];
                af[mt][2] = As_s[row * PADK + kb + tid4 + 4];
                af[mt][3] = As_s[(row + 8) * PADK + kb + tid4 + 4];
            }
#pragma unroll
            for (int nt = 0; nt < 4; nt++) {
                int col = warp_n * 32 + nt * 8 + gid;
                uint32_t b0 = Bs_s[col * PADK + kb + tid4];
                uint32_t b1 = Bs_s[col * PADK + kb + tid4 + 4];
#pragma unroll
                for (int mt = 0; mt < 2; mt++)
                    mma_tf32(acc[mt][nt], af[mt], b0, b1);
            }
        }
    }
#undef ISSUE

#pragma unroll
    for (int mt = 0; mt < 2; mt++) {
        int srow = s0 + warp_m * 32 + mt * 16 + gid;
#pragma unroll
        for (int nt = 0; nt < 4; nt++) {
            int hcol = h0 + warp_n * 32 + nt * 8 + 2 * tid4;
            float2 v0 = make_float2(acc[mt][nt][0], acc[mt][nt][1]);
            float2 v1 = make_float2(acc[mt][nt][2], acc[mt][nt][3]);
            *(float2*)&g_C[(size_t)srow * H + hcol]       = v0;
            *(float2*)&g_C[(size_t)(srow + 8) * H + hcol] = v1;
        }
    }
}

// ---------------- K4: score epilogue: warp-per-row + global exp-sum atomic ----
// grid 256 x 256 (8 warps/block -> 8 rows/block)
__global__ void k_score(const float* __restrict__ v) {
    int wid  = threadIdx.x >> 5;
    int lane = threadIdx.x & 31;
    int row  = blockIdx.x * 8 + wid;

    const float4* c4 = (const float4*)(g_C + (size_t)row * H);
    const float4* u4 = (const float4*)g_u;
    const float4* v4 = (const float4*)v;

    float p = 0.f;
#pragma unroll
    for (int q = 0; q < 8; q++) {
        int k = lane + 32 * q;
        float4 c = c4[k]; float4 u = u4[k]; float4 vv = v4[k];
        p += vv.x * tanhf(c.x + u.x) + vv.y * tanhf(c.y + u.y)
           + vv.z * tanhf(c.z + u.z) + vv.w * tanhf(c.w + u.w);
    }
    p = warp_sum(p);
    if (lane == 0) {
        g_scores[row] = p;
        atomicAdd(&g_sumexp, expf(p));    // scores bounded by ~51 -> no overflow
    }
}

// ---------------- K5: context = softmax(scores) @ enc  (w computed inline) ----------
__global__ void k_ctx(const float* __restrict__ enc, float* __restrict__ out) {
    __shared__ float sw[64];
    int tid = threadIdx.x;
    int e   = blockIdx.x * 256 + tid;
    int s0c = blockIdx.y * 64;
    if (tid < 64) {
        float w = expf(g_scores[s0c + tid]) / g_sumexp;
        sw[tid] = w;
        if (blockIdx.x == 0) out[V + 3 * H + s0c + tid] = w;
    }
    __syncthreads();
    float acc = 0.f;
#pragma unroll 8
    for (int s = 0; s < 64; s++)
        acc += sw[s] * enc[(size_t)(s0c + s) * E + e];
    atomicAdd(&g_context[e], acc);
}

// ---------------- K6: x_t = tanh(W_ah @ [context, h] + b_ah) ----------------
__global__ void k_xt(const float* __restrict__ W_ah, const float* __restrict__ b_ah,
                     float* __restrict__ out) {
    int r    = blockIdx.x * 8 + (threadIdx.x >> 5);
    int lane = threadIdx.x & 31;
    const float4* wa4 = (const float4*)(W_ah + (size_t)r * (E + H));
    const float4* c4  = (const float4*)g_context;
    const float4* h4  = (const float4*)g_h;
    float s = 0.f;
#pragma unroll
    for (int q = 0; q < 8; q++) {
        int k = lane + 32 * q;
        float4 a = wa4[k];        float4 b = c4[k];
        s += a.x * b.x + a.y * b.y + a.z * b.z + a.w * b.w;
        float4 a2 = wa4[256 + k]; float4 b2 = h4[k];
        s += a2.x * b2.x + a2.y * b2.y + a2.z * b2.z + a2.w * b2.w;
    }
    s = warp_sum(s);
    if (lane == 0) {
        float xt = tanhf(s + b_ah[r]);
        g_xt[r] = xt;
        out[V + 2 * H + r] = xt;
    }
}

// ---------------- K7: logits = W_out @ x_t + b_out, + per-block exp-sum partials ----
__global__ void k_logits(const float* __restrict__ W_out, const float* __restrict__ b_out,
                         float* __restrict__ out) {
    __shared__ float sred[8];
    int tid  = threadIdx.x;
    int wid  = tid >> 5;
    int lane = tid & 31;
    int r    = blockIdx.x * 8 + wid;
    const float4* w4 = (const float4*)(W_out + (size_t)r * H);
    const float4* x4 = (const float4*)g_xt;
    float s = 0.f;
#pragma unroll
    for (int q = 0; q < 8; q++) {
        int k = lane + 32 * q;
        float4 a = w4[k]; float4 b = x4[k];
        s += a.x * b.x + a.y * b.y + a.z * b.z + a.w * b.w;
    }
    s = warp_sum(s);
    if (lane == 0) {
        float val = s + b_out[r];
        out[r] = val;
        sred[wid] = expf(val);
    }
    __syncthreads();
    if (tid == 0) {
        float p = 0.f;
#pragma unroll
        for (int i = 0; i < 8; i++) p += sred[i];
        g_lp[blockIdx.x] = p;
    }
}

// ---------------- K8: log-softmax ----------------
__global__ void k_logsoftmax(float* __restrict__ out) {
    __shared__ float red[256];
    int tid = threadIdx.x;
    float p = 0.f;
    for (int i = tid; i < NLOGB; i += 256) p += g_lp[i];
    red[tid] = p; __syncthreads();
    for (int o = 128; o; o >>= 1) { if (tid < o) red[tid] += red[tid + o]; __syncthreads(); }
    float l = logf(red[0]);
    int i = blockIdx.x * 256 + tid;
    out[i] = out[i] - l;
}

// ---------------- launch (R8-identical allocation footprint: 1 stream, 2 events) ----
extern "C" void kernel_launch(void* const* d_in, const int* in_sizes, int n_in,
                              void* d_out, int out_size) {
    const float* enc      = (const float*)d_in[0];
    const int*   word     = (const int*)  d_in[1];
    const float* last_ctx = (const float*)d_in[2];
    const float* h0       = (const float*)d_in[3];
    const float* c0       = (const float*)d_in[4];
    const float* emb      = (const float*)d_in[5];
    const float* W_ih     = (const float*)d_in[6];
    const float* b_ih     = (const float*)d_in[7];
    const float* W_hh     = (const float*)d_in[8];
    const float* b_hh     = (const float*)d_in[9];
    const float* W_att    = (const float*)d_in[10];
    const float* b_att    = (const float*)d_in[11];
    const float* v        = (const float*)d_in[12];
    const float* W_ah     = (const float*)d_in[13];
    const float* b_ah     = (const float*)d_in[14];
    const float* W_out    = (const float*)d_in[15];
    const float* b_out    = (const float*)d_in[16];
    float* out = (float*)d_out;

    cudaFuncSetAttribute(k_att_gemm, cudaFuncAttributeMaxDynamicSharedMemorySize, ATT_SMEM_BYTES);

    // fork: prefetch + LSTM chain on side stream, attention GEMM on main stream
    cudaStream_t sB;
    cudaStreamCreateWithFlags(&sB, cudaStreamNonBlocking);
    cudaEvent_t e0, eB;
    cudaEventCreateWithFlags(&e0, cudaEventDisableTiming);
    cudaEventCreateWithFlags(&eB, cudaEventDisableTiming);

    cudaEventRecord(e0, 0);
    cudaStreamWaitEvent(sB, e0, 0);
    k_prefetch<<<768, 256, 0, sB>>>(W_out);
    k_gates<<<512, 256, 0, sB>>>(W_ih, b_ih, W_hh, b_hh, last_ctx, emb, word, h0);
    k_cell_u<<<128, 256, 0, sB>>>(c0, W_att, b_att, out);
    cudaEventRecord(eB, sB);

    dim3 g3(S / BM, H / BN);
    k_att_gemm<<<g3, 256, ATT_SMEM_BYTES>>>(enc, W_att);

    cudaStreamWaitEvent(0, eB, 0);
    k_score<<<S / 8, 256>>>(v);
    dim3 g5(E / 256, S / 64);
    k_ctx<<<g5, 256>>>(enc, out);
    k_xt<<<128, 256>>>(W_ah, b_ah, out);
    k_logits<<<NLOGB, 256>>>(W_out, b_out, out);
    k_logsoftmax<<<V / 256, 256>>>(out);
}